// round 5
// baseline (speedup 1.0000x reference)
#include <cuda_runtime.h>
#include <cstdint>

#define NSLOTS 8
#define NKEYS  8192
#define KDIM   256
#define VDIM   512
#define NQ     4096
#define IN_DIM 512
#define TOPK   32
#define CHUNK  128
#define NCHUNK (NKEYS / CHUNK)        // 64
#define NSTAGE (NCHUNK * 8)           // 512 stages of 128 keys x 32 dims

__device__ float g_q[NQ * KDIM];                    // 4 MB
__device__ float g_resid[NQ * VDIM];                // 8 MB
__device__ float g_keysn[NSLOTS * NKEYS * KDIM];    // 64 MB normalized tf32 keys (dim-pair permuted)

// ---------------------------------------------------------------------------
// fp32 GEMM (NT): C = A·Bᵀ + bias. BM=64,BN=64,BK=16,TM=8,TN=4, 128 thr.
// ---------------------------------------------------------------------------
__global__ __launch_bounds__(128) void gemm_nt_bias(
    const float* __restrict__ A, const float* __restrict__ B,
    const float* __restrict__ bias, float* __restrict__ C,
    int M, int N, int K)
{
    __shared__ float As[16][68];
    __shared__ float Bs[16][68];
    const int tid = threadIdx.x;
    const int tx = tid & 15, ty = tid >> 4;
    const int m0 = blockIdx.y * 64, n0 = blockIdx.x * 64;

    float acc[8][4];
#pragma unroll
    for (int i = 0; i < 8; i++)
#pragma unroll
        for (int j = 0; j < 4; j++) acc[i][j] = 0.f;

    for (int k0 = 0; k0 < K; k0 += 16) {
        __syncthreads();
#pragma unroll
        for (int i = 0; i < 2; i++) {
            int f = tid + i * 128;
            int r = f >> 2, q4 = (f & 3) << 2;
            float4 va = *(const float4*)(A + (size_t)(m0 + r) * K + k0 + q4);
            As[q4 + 0][r] = va.x; As[q4 + 1][r] = va.y;
            As[q4 + 2][r] = va.z; As[q4 + 3][r] = va.w;
            float4 vb = *(const float4*)(B + (size_t)(n0 + r) * K + k0 + q4);
            Bs[q4 + 0][r] = vb.x; Bs[q4 + 1][r] = vb.y;
            Bs[q4 + 2][r] = vb.z; Bs[q4 + 3][r] = vb.w;
        }
        __syncthreads();
#pragma unroll
        for (int k = 0; k < 16; k++) {
            float4 a0 = *(const float4*)&As[k][ty * 8];
            float4 a1 = *(const float4*)&As[k][ty * 8 + 4];
            float4 b  = *(const float4*)&Bs[k][tx * 4];
            float av[8] = {a0.x, a0.y, a0.z, a0.w, a1.x, a1.y, a1.z, a1.w};
            float bv[4] = {b.x, b.y, b.z, b.w};
#pragma unroll
            for (int i = 0; i < 8; i++)
#pragma unroll
                for (int j = 0; j < 4; j++) acc[i][j] += av[i] * bv[j];
        }
    }
    const int n = n0 + tx * 4;
    float4 bb = *(const float4*)(bias + n);
#pragma unroll
    for (int i = 0; i < 8; i++) {
        float4 o = make_float4(acc[i][0] + bb.x, acc[i][1] + bb.y,
                               acc[i][2] + bb.z, acc[i][3] + bb.w);
        *(float4*)(C + (size_t)(m0 + ty * 8 + i) * N + n) = o;
    }
}

// ---------------------------------------------------------------------------
__device__ __forceinline__ unsigned f2tf32(float x) {
    unsigned u;
    asm("cvt.rna.tf32.f32 %0, %1;" : "=r"(u) : "f"(x));
    return u;
}
__device__ __forceinline__ float tf32r(float x) { return __uint_as_float(f2tf32(x)); }

// keys -> normalized, tf32-rounded, DIM-PAIR PERMUTED within each 8-dim block:
// positions (2t, 2t+1) hold dims (t, t+4). Dot products are invariant since q
// uses the same permutation. One warp per key; lane handles one 8-dim block.
__global__ __launch_bounds__(256) void normalize_keys(
    const float* __restrict__ keys, float* __restrict__ kn)
{
    const int lane = threadIdx.x & 31;
    const int key = blockIdx.x * 8 + (threadIdx.x >> 5);
    const float4* kp = (const float4*)(keys + (size_t)key * KDIM);
    float4 v0 = kp[2 * lane], v1 = kp[2 * lane + 1];
    float s = v0.x * v0.x + v0.y * v0.y + v0.z * v0.z + v0.w * v0.w
            + v1.x * v1.x + v1.y * v1.y + v1.z * v1.z + v1.w * v1.w;
#pragma unroll
    for (int o = 16; o; o >>= 1) s += __shfl_xor_sync(0xffffffffu, s, o);
    float inv = rsqrtf(s);
    float4* op = (float4*)(kn + (size_t)key * KDIM);
    op[2 * lane]     = make_float4(tf32r(v0.x * inv), tf32r(v1.x * inv),
                                   tf32r(v0.y * inv), tf32r(v1.y * inv));
    op[2 * lane + 1] = make_float4(tf32r(v0.z * inv), tf32r(v1.z * inv),
                                   tf32r(v0.w * inv), tf32r(v1.w * inv));
}

// ---------------------------------------------------------------------------
__device__ __forceinline__ void mma_tf32(float c[4], const unsigned a[4],
                                         unsigned b0, unsigned b1) {
    asm volatile(
        "mma.sync.aligned.m16n8k8.row.col.f32.tf32.tf32.f32 "
        "{%0,%1,%2,%3}, {%4,%5,%6,%7}, {%8,%9}, {%0,%1,%2,%3};\n"
        : "+f"(c[0]), "+f"(c[1]), "+f"(c[2]), "+f"(c[3])
        : "r"(a[0]), "r"(a[1]), "r"(a[2]), "r"(a[3]), "r"(b0), "r"(b1));
}

// packed score|idx (order-preserving), 19 score bits + 13 index bits
__device__ __forceinline__ unsigned packscore(float f, int idx) {
    unsigned u = __float_as_uint(f);
    u = ((int)u >= 0) ? (u | 0x80000000u) : ~u;
    return (u & 0xFFFFE000u) | (unsigned)idx;
}
__device__ __forceinline__ float unpackscore(unsigned p) {
    unsigned bits = (p & 0x80000000u) ? (p & 0x7FFFFFFFu) : ~p;
    bits = (bits & 0xFFFFE000u) | 0x1000u;
    return __uint_as_float(bits);
}

__device__ __forceinline__ void mbar_wait(uint32_t mbar, uint32_t parity) {
    asm volatile(
        "{\n\t.reg .pred P;\n"
        "W_%=:\n\t"
        "mbarrier.try_wait.parity.acquire.cta.shared::cta.b64 P, [%0], %1, 0x989680;\n\t"
        "@P bra D_%=;\n\t"
        "bra W_%=;\n"
        "D_%=:\n\t}"
        :: "r"(mbar), "r"(parity) : "memory");
}

// ---------------------------------------------------------------------------
// smem layout (bytes from dynamic smem base)
// ---------------------------------------------------------------------------
#define SQ_LD 264                            // floats per q row (pad: 264 % 32 == 8)
#define SB_LD 40                             // floats per key row  (40 % 32 == 8)
#define SQ_BYTES (128 * SQ_LD * 4)           // 135168
#define SB_OFF   SQ_BYTES
#define SB_BYTES (CHUNK * SB_LD * 4)         // 20480 per buffer
#define SS_OFF   (SB_OFF + 2 * SB_BYTES)     // 176128
#define SS_LD    65
#define HP_OFF   (SS_OFF + 128 * SS_LD * 4)  // 209408
#define MB_OFF   (HP_OFF + 128 * 33 * 4)     // 226304
#define FUSED_SMEM_BYTES (MB_OFF + 64)       // 226368 (< 227 KB)

// issue cp.async for stage s into buffer s&1, with async arrive on full mbar
__device__ __forceinline__ void issue_stage(
    uint32_t sb, const float* __restrict__ keybase, int tid, int s,
    uint32_t mbF0, uint32_t mbF1)
{
    const int key0 = (s >> 3) * CHUNK;
    const int ds = (s & 7) * 32;
    const uint32_t sbuf = sb + SB_OFF + (uint32_t)(s & 1) * SB_BYTES;
    const float* gb = keybase + (size_t)key0 * KDIM + ds;
#pragma unroll
    for (int i = 0; i < 2; i++) {
        int f = tid + i * 512;                // 1024 float4s per stage
        int key = f >> 3, c4 = (f & 7) << 2;
        uint32_t sa = sbuf + (uint32_t)(key * SB_LD + c4) * 4u;
        const float* ga = gb + (size_t)key * KDIM + c4;
        asm volatile("cp.async.cg.shared.global [%0], [%1], 16;\n"
                     :: "r"(sa), "l"(ga));
    }
    uint32_t mb = (s & 1) ? mbF1 : mbF0;
    asm volatile("cp.async.mbarrier.arrive.noinc.shared.b64 [%0];"
                 :: "r"(mb) : "memory");
}

__global__ __launch_bounds__(512, 1) void fused_slot(
    const float* __restrict__ keysn, const float* __restrict__ values,
    float* __restrict__ out)
{
    extern __shared__ char smem[];
    const uint32_t sb = (uint32_t)__cvta_generic_to_shared(smem);
    float* sQ = (float*)smem;
    unsigned* sS = (unsigned*)(smem + SS_OFF);
    unsigned* hp = (unsigned*)(smem + HP_OFF);
    const uint32_t mbF0 = sb + MB_OFF,      mbF1 = sb + MB_OFF + 8;
    const uint32_t mbE0 = sb + MB_OFF + 16, mbE1 = sb + MB_OFF + 24;

    const int tid  = threadIdx.x;
    const int lane = tid & 31, wid = tid >> 5;
    const int warp_m = wid >> 2;   // 0..3 -> 32 query rows
    const int warp_n = wid & 3;    // 0..3 -> 32 keys of the 128-chunk
    const int g = lane >> 2, tig = lane & 3;
    const int slot = blockIdx.y;
    const int q0 = blockIdx.x * 128;
    const float* keybase = keysn + (size_t)slot * NKEYS * KDIM;

    if (tid == 0) {
        asm volatile("mbarrier.init.shared.b64 [%0], 512;" :: "r"(mbF0) : "memory");
        asm volatile("mbarrier.init.shared.b64 [%0], 512;" :: "r"(mbF1) : "memory");
        asm volatile("mbarrier.init.shared.b64 [%0], 16;"  :: "r"(mbE0) : "memory");
        asm volatile("mbarrier.init.shared.b64 [%0], 16;"  :: "r"(mbE1) : "memory");
    }
    __syncthreads();                         // mbars initialized

    issue_stage(sb, keybase, tid, 0, mbF0, mbF1);
    issue_stage(sb, keybase, tid, 1, mbF0, mbF1);

    // q tile: tf32-rounded, dim-pair permuted (positions 2t,2t+1 <- dims t,t+4)
    const float4* qg4 = (const float4*)(g_q + (size_t)q0 * KDIM);
#pragma unroll
    for (int i = 0; i < 8; i++) {
        int f = tid + i * 512;               // (row, 8-dim block): 128*32
        int row = f >> 5, blk = f & 31;
        float4 v0 = qg4[row * 64 + 2 * blk];
        float4 v1 = qg4[row * 64 + 2 * blk + 1];
        uint4 u0 = make_uint4(f2tf32(v0.x), f2tf32(v1.x), f2tf32(v0.y), f2tf32(v1.y));
        uint4 u1 = make_uint4(f2tf32(v0.z), f2tf32(v1.z), f2tf32(v0.w), f2tf32(v1.w));
        *(uint4*)&sQ[row * SQ_LD + blk * 8]     = u0;
        *(uint4*)&sQ[row * SQ_LD + blk * 8 + 4] = u1;
    }
    for (int i = tid; i < 128 * 33; i += 512) hp[i] = 0u;
    __syncthreads();                         // sQ + heaps visible

    float c[2][4][4];
#pragma unroll
    for (int mm = 0; mm < 2; mm++)
#pragma unroll
        for (int nn = 0; nn < 4; nn++)
#pragma unroll
            for (int r = 0; r < 4; r++) c[mm][nn][r] = 0.f;

    for (int s = 0; s < NSTAGE; s++) {
        const uint32_t mbF = (s & 1) ? mbF1 : mbF0;
        const uint32_t mbE = (s & 1) ? mbE1 : mbE0;
        const uint32_t par = (s >> 1) & 1;
        mbar_wait(mbF, par);                 // stage s data ready

        const float* kbuf = (const float*)(smem + SB_OFF + (s & 1) * SB_BYTES);
        const int ds = (s & 7) * 32;
#pragma unroll
        for (int ks = 0; ks < 4; ks++) {
            const int doff = ds + ks * 8 + 2 * tig;   // permuted: float2 = (t, t+4)
            unsigned a[2][4];
#pragma unroll
            for (int mm = 0; mm < 2; mm++) {
                const int r0 = warp_m * 32 + mm * 16;
                float2 alo = *(const float2*)&sQ[(r0 + g) * SQ_LD + doff];
                float2 ahi = *(const float2*)&sQ[(r0 + g + 8) * SQ_LD + doff];
                a[mm][0] = __float_as_uint(alo.x);
                a[mm][1] = __float_as_uint(ahi.x);
                a[mm][2] = __float_as_uint(alo.y);
                a[mm][3] = __float_as_uint(ahi.y);
            }
#pragma unroll
            for (int nn = 0; nn < 4; nn++) {
                float2 bv = *(const float2*)&kbuf[(warp_n * 32 + nn * 8 + g) * SB_LD
                                                  + ks * 8 + 2 * tig];
                unsigned b0 = __float_as_uint(bv.x);
                unsigned b1 = __float_as_uint(bv.y);
#pragma unroll
                for (int mm = 0; mm < 2; mm++) mma_tf32(c[mm][nn], a[mm], b0, b1);
            }
        }
        __syncwarp();
        if (lane == 0)
            asm volatile("mbarrier.arrive.shared.b64 _, [%0];" :: "r"(mbE) : "memory");
        if (s + 2 < NSTAGE) {
            mbar_wait(mbE, par);             // all 16 warps done with buffer
            issue_stage(sb, keybase, tid, s + 2, mbF0, mbF1);
        }

        if ((s & 7) == 7) {                  // chunk of 128 keys complete
            const int key0 = (s >> 3) * CHUNK;
#pragma unroll
            for (int half = 0; half < 2; half++) {
                if ((warp_n >> 1) == half) {
                    const int cb = (warp_n & 1) * 32;
                    const int ib = key0 + half * 64;
#pragma unroll
                    for (int mm = 0; mm < 2; mm++) {
                        int r0 = warp_m * 32 + mm * 16 + g;
#pragma unroll
                        for (int nn = 0; nn < 4; nn++) {
                            int col = cb + nn * 8 + 2 * tig;
                            sS[r0 * SS_LD + col]           = packscore(c[mm][nn][0], ib + col);
                            sS[r0 * SS_LD + col + 1]       = packscore(c[mm][nn][1], ib + col + 1);
                            sS[(r0 + 8) * SS_LD + col]     = packscore(c[mm][nn][2], ib + col);
                            sS[(r0 + 8) * SS_LD + col + 1] = packscore(c[mm][nn][3], ib + col + 1);
                        }
                    }
                }
                __syncthreads();
                if (tid < 128) {
                    unsigned* h = hp + tid * 33;
                    const unsigned* srow = sS + tid * SS_LD;
                    unsigned hmin = h[0];
#pragma unroll 4
                    for (int j = 0; j < 64; j++) {
                        unsigned v = srow[j];
                        if (v > hmin) {
                            int p = 0;
                            while (true) {
                                int cl = 2 * p + 1;
                                if (cl >= TOPK) break;
                                int cr = cl + 1;
                                if (cr < TOPK && h[cr] < h[cl]) cl = cr;
                                if (h[cl] >= v) break;
                                h[p] = h[cl]; p = cl;
                            }
                            h[p] = v;
                            hmin = h[0];
                        }
                    }
                }
                __syncthreads();
            }
#pragma unroll
            for (int mm = 0; mm < 2; mm++)
#pragma unroll
                for (int nn = 0; nn < 4; nn++)
#pragma unroll
                    for (int r = 0; r < 4; r++) c[mm][nn][r] = 0.f;
        }
    }

    // softmax over top-32 + weighted value gather + residual (8 queries/warp)
    const float* vbase = values + (size_t)slot * NKEYS * VDIM;
#pragma unroll
    for (int t = 0; t < 8; t++) {
        const int q = wid * 8 + t;
        const int qg_ = q0 + q;
        unsigned p = hp[q * 33 + lane];
        float s = unpackscore(p);
        int  ki = (int)(p & 0x1FFFu);
        float m = s;
#pragma unroll
        for (int o = 16; o; o >>= 1)
            m = fmaxf(m, __shfl_xor_sync(0xffffffffu, m, o));
        float e = __expf(s - m);
        float sum = e;
#pragma unroll
        for (int o = 16; o; o >>= 1) sum += __shfl_xor_sync(0xffffffffu, sum, o);
        float w = e / sum;

        float4 acc[4];
#pragma unroll
        for (int j = 0; j < 4; j++) acc[j] = make_float4(0.f, 0.f, 0.f, 0.f);
#pragma unroll 4
        for (int k = 0; k < TOPK; k++) {
            float wk = __shfl_sync(0xffffffffu, w, k);
            int   ik = __shfl_sync(0xffffffffu, ki, k);
            const float4* vr = (const float4*)(vbase + (size_t)ik * VDIM);
#pragma unroll
            for (int j = 0; j < 4; j++) {
                float4 v = vr[lane + j * 32];
                acc[j].x += wk * v.x; acc[j].y += wk * v.y;
                acc[j].z += wk * v.z; acc[j].w += wk * v.w;
            }
        }
        const float4* rr = (const float4*)(g_resid + (size_t)qg_ * VDIM);
        float4* op = (float4*)(out + ((size_t)qg_ * NSLOTS + slot) * VDIM);
#pragma unroll
        for (int j = 0; j < 4; j++) {
            float4 r = rr[lane + j * 32];
            op[lane + j * 32] = make_float4(acc[j].x + r.x, acc[j].y + r.y,
                                            acc[j].z + r.z, acc[j].w + r.w);
        }
    }
}

// ---------------------------------------------------------------------------
extern "C" void kernel_launch(void* const* d_in, const int* in_sizes, int n_in,
                              void* d_out, int out_size)
{
    const float* x      = (const float*)d_in[0];
    const float* keys   = (const float*)d_in[1];
    const float* values = (const float*)d_in[2];
    const float* wq     = (const float*)d_in[3];
    const float* bq     = (const float*)d_in[4];
    const float* wr     = (const float*)d_in[5];
    const float* br     = (const float*)d_in[6];
    float* out = (float*)d_out;

    float *qp, *rp, *kp;
    cudaGetSymbolAddress((void**)&qp, g_q);
    cudaGetSymbolAddress((void**)&rp, g_resid);
    cudaGetSymbolAddress((void**)&kp, g_keysn);

    normalize_keys<<<NSLOTS * NKEYS / 8, 256>>>(keys, kp);
    gemm_nt_bias<<<dim3(KDIM / 64, NQ / 64), 128>>>(x, wq, bq, qp, NQ, KDIM, IN_DIM);
    gemm_nt_bias<<<dim3(VDIM / 64, NQ / 64), 128>>>(qp, wr, br, rp, NQ, VDIM, KDIM);

    cudaFuncSetAttribute(fused_slot,
                         cudaFuncAttributeMaxDynamicSharedMemorySize,
                         FUSED_SMEM_BYTES);
    fused_slot<<<dim3(NQ / 128, NSLOTS), 512, FUSED_SMEM_BYTES>>>(kp, values, out);
}

// round 7
// speedup vs baseline: 1.2572x; 1.2572x over previous
#include <cuda_runtime.h>
#include <cuda_fp16.h>
#include <cstdint>

#define NSLOTS 8
#define NKEYS  8192
#define KDIM   256
#define VDIM   512
#define NQ     4096
#define IN_DIM 512
#define TOPK   32
#define CHUNK  128
#define NCHUNK (NKEYS / CHUNK)        // 64
#define NSTAGE (NCHUNK * 4)           // 256 stages: 128 keys x 64 dims each

__device__ float  g_q[NQ * KDIM];                      // 4 MB fp32 (exact)
__device__ float  g_resid[NQ * VDIM];                  // 8 MB fp32 (exact)
__device__ __half g_keysh[NSLOTS * NKEYS * KDIM];      // 33.5 MB normalized fp16, stage-blocked
__device__ __half g_valh[NSLOTS * NKEYS * VDIM];       // 67 MB fp16 values

// ---------------------------------------------------------------------------
// fp32 GEMM (NT): C = A·Bᵀ + bias. BM=64,BN=64,BK=16,TM=8,TN=4, 128 thr.
// ---------------------------------------------------------------------------
__global__ __launch_bounds__(128) void gemm_nt_bias(
    const float* __restrict__ A, const float* __restrict__ B,
    const float* __restrict__ bias, float* __restrict__ C,
    int M, int N, int K)
{
    __shared__ float As[16][68];
    __shared__ float Bs[16][68];
    const int tid = threadIdx.x;
    const int tx = tid & 15, ty = tid >> 4;
    const int m0 = blockIdx.y * 64, n0 = blockIdx.x * 64;

    float acc[8][4];
#pragma unroll
    for (int i = 0; i < 8; i++)
#pragma unroll
        for (int j = 0; j < 4; j++) acc[i][j] = 0.f;

    for (int k0 = 0; k0 < K; k0 += 16) {
        __syncthreads();
#pragma unroll
        for (int i = 0; i < 2; i++) {
            int f = tid + i * 128;
            int r = f >> 2, q4 = (f & 3) << 2;
            float4 va = *(const float4*)(A + (size_t)(m0 + r) * K + k0 + q4);
            As[q4 + 0][r] = va.x; As[q4 + 1][r] = va.y;
            As[q4 + 2][r] = va.z; As[q4 + 3][r] = va.w;
            float4 vb = *(const float4*)(B + (size_t)(n0 + r) * K + k0 + q4);
            Bs[q4 + 0][r] = vb.x; Bs[q4 + 1][r] = vb.y;
            Bs[q4 + 2][r] = vb.z; Bs[q4 + 3][r] = vb.w;
        }
        __syncthreads();
#pragma unroll
        for (int k = 0; k < 16; k++) {
            float4 a0 = *(const float4*)&As[k][ty * 8];
            float4 a1 = *(const float4*)&As[k][ty * 8 + 4];
            float4 b  = *(const float4*)&Bs[k][tx * 4];
            float av[8] = {a0.x, a0.y, a0.z, a0.w, a1.x, a1.y, a1.z, a1.w};
            float bv[4] = {b.x, b.y, b.z, b.w};
#pragma unroll
            for (int i = 0; i < 8; i++)
#pragma unroll
                for (int j = 0; j < 4; j++) acc[i][j] += av[i] * bv[j];
        }
    }
    const int n = n0 + tx * 4;
    float4 bb = *(const float4*)(bias + n);
#pragma unroll
    for (int i = 0; i < 8; i++) {
        float4 o = make_float4(acc[i][0] + bb.x, acc[i][1] + bb.y,
                               acc[i][2] + bb.z, acc[i][3] + bb.w);
        *(float4*)(C + (size_t)(m0 + ty * 8 + i) * N + n) = o;
    }
}

// ---------------------------------------------------------------------------
// keys -> normalized fp16, stage-blocked layout:
//   [slot][stage = chunk*4 + dimblock][key 0..127][dim 0..63]
// one warp per key; lane handles 8 dims.
// ---------------------------------------------------------------------------
__global__ __launch_bounds__(256) void normalize_keys_h(
    const float* __restrict__ keys, __half* __restrict__ kh)
{
    const int lane = threadIdx.x & 31;
    const int key = blockIdx.x * 8 + (threadIdx.x >> 5);
    const int slot = key / NKEYS, kk = key % NKEYS;
    const int chunk = kk >> 7, keyin = kk & 127;
    const float4* kp = (const float4*)(keys + (size_t)key * KDIM);
    float4 v0 = kp[2 * lane], v1 = kp[2 * lane + 1];
    float s = v0.x * v0.x + v0.y * v0.y + v0.z * v0.z + v0.w * v0.w
            + v1.x * v1.x + v1.y * v1.y + v1.z * v1.z + v1.w * v1.w;
#pragma unroll
    for (int o = 16; o; o >>= 1) s += __shfl_xor_sync(0xffffffffu, s, o);
    float inv = rsqrtf(s);

    __half2 p0 = __floats2half2_rn(v0.x * inv, v0.y * inv);
    __half2 p1 = __floats2half2_rn(v0.z * inv, v0.w * inv);
    __half2 p2 = __floats2half2_rn(v1.x * inv, v1.y * inv);
    __half2 p3 = __floats2half2_rn(v1.z * inv, v1.w * inv);
    uint4 u = make_uint4(*(unsigned*)&p0, *(unsigned*)&p1,
                         *(unsigned*)&p2, *(unsigned*)&p3);
    size_t dst = (size_t)slot * (NKEYS * KDIM)
               + (size_t)(chunk * 4 + (lane >> 3)) * (128 * 64)
               + (size_t)keyin * 64 + ((lane * 8) & 63);
    *(uint4*)(kh + dst) = u;
}

// values fp32 -> fp16 (8 elems/thread)
__global__ __launch_bounds__(256) void values_to_half(
    const float* __restrict__ v, __half* __restrict__ vh)
{
    size_t i = ((size_t)blockIdx.x * 256 + threadIdx.x) * 8;
    float4 a = *(const float4*)(v + i);
    float4 b = *(const float4*)(v + i + 4);
    __half2 p0 = __floats2half2_rn(a.x, a.y);
    __half2 p1 = __floats2half2_rn(a.z, a.w);
    __half2 p2 = __floats2half2_rn(b.x, b.y);
    __half2 p3 = __floats2half2_rn(b.z, b.w);
    uint4 u = make_uint4(*(unsigned*)&p0, *(unsigned*)&p1,
                         *(unsigned*)&p2, *(unsigned*)&p3);
    *(uint4*)(vh + i) = u;
}

// ---------------------------------------------------------------------------
__device__ __forceinline__ void mma_f16(float c[4],
    unsigned a0, unsigned a1, unsigned a2, unsigned a3,
    unsigned b0, unsigned b1)
{
    asm volatile(
        "mma.sync.aligned.m16n8k16.row.col.f32.f16.f16.f32 "
        "{%0,%1,%2,%3}, {%4,%5,%6,%7}, {%8,%9}, {%0,%1,%2,%3};"
        : "+f"(c[0]), "+f"(c[1]), "+f"(c[2]), "+f"(c[3])
        : "r"(a0), "r"(a1), "r"(a2), "r"(a3), "r"(b0), "r"(b1));
}

__device__ __forceinline__ void ldsm4(unsigned r[4], uint32_t addr) {
    asm volatile("ldmatrix.sync.aligned.m8n8.x4.shared.b16 {%0,%1,%2,%3}, [%4];"
                 : "=r"(r[0]), "=r"(r[1]), "=r"(r[2]), "=r"(r[3]) : "r"(addr));
}

// packed score|idx (order-preserving), 19 score bits + 13 index bits
__device__ __forceinline__ unsigned packscore(float f, int idx) {
    unsigned u = __float_as_uint(f);
    u = ((int)u >= 0) ? (u | 0x80000000u) : ~u;
    return (u & 0xFFFFE000u) | (unsigned)idx;
}
__device__ __forceinline__ float unpackscore(unsigned p) {
    unsigned bits = (p & 0x80000000u) ? (p & 0x7FFFFFFFu) : ~p;
    bits = (bits & 0xFFFFE000u) | 0x1000u;
    return __uint_as_float(bits);
}

__device__ __forceinline__ void mbar_wait(uint32_t mbar, uint32_t parity) {
    asm volatile(
        "{\n\t.reg .pred P;\n"
        "W_%=:\n\t"
        "mbarrier.try_wait.parity.acquire.cta.shared::cta.b64 P, [%0], %1, 0x989680;\n\t"
        "@P bra D_%=;\n\t"
        "bra W_%=;\n"
        "D_%=:\n\t}"
        :: "r"(mbar), "r"(parity) : "memory");
}

// ---------------------------------------------------------------------------
// smem layout (bytes):
//   sQ  128 rows x 264 halves (stride 528B, ldmatrix conflict-free)  67584
//   sB  3 buffers x (128 keys x 72 halves, stride 144B)              55296
//   sS  128 x 129 u32                                                66048
//   hp  128 x 33 u32                                                 16896
//   mbars: full[3] + empty[3]                                           48
// ---------------------------------------------------------------------------
#define SQ_STRIDE_B 528
#define SB_STRIDE_B 144
#define SB_OFF   67584
#define SB_BYTES 18432
#define SS_OFF   (SB_OFF + 3 * SB_BYTES)      // 122880
#define SS_LD    129
#define HP_OFF   (SS_OFF + 128 * SS_LD * 4)   // 188928
#define MB_OFF   (HP_OFF + 128 * 33 * 4)      // 205824
#define FUSED_SMEM_BYTES (MB_OFF + 48)        // 205872

__device__ __forceinline__ void issue_stage_h(
    uint32_t sb, const __half* __restrict__ keybase, int tid, int t, int t3)
{
    const __half* gb = keybase + (size_t)t * (128 * 64);
    const uint32_t sbuf = sb + SB_OFF + (uint32_t)t3 * SB_BYTES;
#pragma unroll
    for (int i = 0; i < 2; i++) {
        int f = tid + i * 512;
        uint32_t sa = sbuf + (uint32_t)((f >> 3) * SB_STRIDE_B + (f & 7) * 16);
        const __half* ga = gb + f * 8;
        asm volatile("cp.async.cg.shared.global [%0], [%1], 16;\n"
                     :: "r"(sa), "l"(ga));
    }
    uint32_t mb = sb + MB_OFF + (uint32_t)t3 * 8;
    asm volatile("cp.async.mbarrier.arrive.noinc.shared.b64 [%0];"
                 :: "r"(mb) : "memory");
}

__global__ __launch_bounds__(512, 1) void fused_slot(
    const __half* __restrict__ keysh, const __half* __restrict__ valh,
    float* __restrict__ out)
{
    extern __shared__ char smem[];
    const uint32_t sb = (uint32_t)__cvta_generic_to_shared(smem);
    __half* sQ = (__half*)smem;
    unsigned* sS = (unsigned*)(smem + SS_OFF);
    unsigned* hp = (unsigned*)(smem + HP_OFF);

    const int tid  = threadIdx.x;
    const int lane = tid & 31, wid = tid >> 5;
    const int warp_m = wid >> 2;     // 0..3 -> 32 query rows
    const int warp_n = wid & 3;      // 0..3 -> 32 keys
    const int g = lane >> 2, tig = lane & 3;
    const int slot = blockIdx.y;
    const int q0 = blockIdx.x * 128;
    const __half* keybase = keysh + (size_t)slot * NKEYS * KDIM;

    // ldmatrix per-lane source row/col
    const int lrow = (lane & 7) + ((lane >> 3) & 1) * 8;   // 0..15
    const int lcolb = (lane >> 4) * 16;                     // byte offset 0/16
    const uint32_t aBase = sb + (uint32_t)((warp_m * 32 + lrow) * SQ_STRIDE_B) + lcolb;
    const uint32_t bOff  = (uint32_t)((warp_n * 32 + lrow) * SB_STRIDE_B) + lcolb;

    if (tid == 0) {
#pragma unroll
        for (int i = 0; i < 3; i++) {
            asm volatile("mbarrier.init.shared.b64 [%0], 512;"
                         :: "r"(sb + MB_OFF + i * 8) : "memory");
            asm volatile("mbarrier.init.shared.b64 [%0], 16;"
                         :: "r"(sb + MB_OFF + 24 + i * 8) : "memory");
        }
    }
    __syncthreads();

    issue_stage_h(sb, keybase, tid, 0, 0);
    issue_stage_h(sb, keybase, tid, 1, 1);

    // q tile: fp32 -> fp16, row stride 264 halves
    const float4* qg4 = (const float4*)(g_q + (size_t)q0 * KDIM);
#pragma unroll
    for (int i = 0; i < 16; i++) {
        int f = tid + i * 512;                 // 8192 float4s
        int row = f >> 6, c4 = (f & 63) << 2;
        float4 v = qg4[f];
        __half2 h0 = __floats2half2_rn(v.x, v.y);
        __half2 h1 = __floats2half2_rn(v.z, v.w);
        *(uint2*)(sQ + row * 264 + c4) = make_uint2(*(unsigned*)&h0, *(unsigned*)&h1);
    }
    for (int i = tid; i < 128 * 33; i += 512) hp[i] = 0u;
    __syncthreads();

    float c[2][4][4];
#pragma unroll
    for (int mm = 0; mm < 2; mm++)
#pragma unroll
        for (int nn = 0; nn < 4; nn++)
#pragma unroll
            for (int r = 0; r < 4; r++) c[mm][nn][r] = 0.f;

    int s3 = 0, sp = 0;          // stage buffer idx, full parity
    int t3 = 2, tph = 0;         // issue stage t=s+2: buffer idx, (t/3)&1

    for (int s = 0; s < NSTAGE; s++) {
        mbar_wait(sb + MB_OFF + s3 * 8, (uint32_t)sp);       // full[s]

        const uint32_t kbA = sb + SB_OFF + (uint32_t)s3 * SB_BYTES + bOff;
        // CRITICAL: q fragment must use this stage's 64-dim window
        const uint32_t aA  = aBase + (uint32_t)(s & 3) * 128;
#pragma unroll
        for (int ks = 0; ks < 4; ks++) {
            const uint32_t ko = ks * 32;                     // 16 halves
            unsigned A0[4], A1[4], B0[4], B1[4];
            ldsm4(A0, aA + ko);
            ldsm4(A1, aA + 16 * SQ_STRIDE_B + ko);
            ldsm4(B0, kbA + ko);
            ldsm4(B1, kbA + 16 * SB_STRIDE_B + ko);
            mma_f16(c[0][0], A0[0], A0[1], A0[2], A0[3], B0[0], B0[2]);
            mma_f16(c[0][1], A0[0], A0[1], A0[2], A0[3], B0[1], B0[3]);
            mma_f16(c[0][2], A0[0], A0[1], A0[2], A0[3], B1[0], B1[2]);
            mma_f16(c[0][3], A0[0], A0[1], A0[2], A0[3], B1[1], B1[3]);
            mma_f16(c[1][0], A1[0], A1[1], A1[2], A1[3], B0[0], B0[2]);
            mma_f16(c[1][1], A1[0], A1[1], A1[2], A1[3], B0[1], B0[3]);
            mma_f16(c[1][2], A1[0], A1[1], A1[2], A1[3], B1[0], B1[2]);
            mma_f16(c[1][3], A1[0], A1[1], A1[2], A1[3], B1[1], B1[3]);
        }
        __syncwarp();
        if (lane == 0)
            asm volatile("mbarrier.arrive.shared.b64 _, [%0];"
                         :: "r"(sb + MB_OFF + 24 + s3 * 8) : "memory");

        const int t = s + 2;
        if (t < NSTAGE) {
            if (t >= 3)
                mbar_wait(sb + MB_OFF + 24 + t3 * 8, (uint32_t)(tph ^ 1));
            issue_stage_h(sb, keybase, tid, t, t3);
        }
        if (++t3 == 3) { t3 = 0; tph ^= 1; }

        if ((s & 3) == 3) {                  // chunk of 128 keys complete
            const int key0 = (s >> 2) << 7;
            __syncthreads();                 // all MMA done, sS free
            {
                const int cb = warp_n * 32;
#pragma unroll
                for (int mm = 0; mm < 2; mm++) {
                    int r0 = warp_m * 32 + mm * 16 + g;
#pragma unroll
                    for (int nn = 0; nn < 4; nn++) {
                        int col = cb + nn * 8 + 2 * tig;
                        sS[r0 * SS_LD + col]           = packscore(c[mm][nn][0], key0 + col);
                        sS[r0 * SS_LD + col + 1]       = packscore(c[mm][nn][1], key0 + col + 1);
                        sS[(r0 + 8) * SS_LD + col]     = packscore(c[mm][nn][2], key0 + col);
                        sS[(r0 + 8) * SS_LD + col + 1] = packscore(c[mm][nn][3], key0 + col + 1);
                    }
                }
            }
            __syncthreads();
            if (tid < 128) {
                unsigned* h = hp + tid * 33;
                const unsigned* srow = sS + tid * SS_LD;
                unsigned hmin = h[0];
#pragma unroll 4
                for (int j = 0; j < 128; j++) {
                    unsigned v = srow[j];
                    if (v > hmin) {
                        int p = 0;
                        while (true) {
                            int cl = 2 * p + 1;
                            if (cl >= TOPK) break;
                            int cr = cl + 1;
                            if (cr < TOPK && h[cr] < h[cl]) cl = cr;
                            if (h[cl] >= v) break;
                            h[p] = h[cl]; p = cl;
                        }
                        h[p] = v;
                        hmin = h[0];
                    }
                }
            }
#pragma unroll
            for (int mm = 0; mm < 2; mm++)
#pragma unroll
                for (int nn = 0; nn < 4; nn++)
#pragma unroll
                    for (int r = 0; r < 4; r++) c[mm][nn][r] = 0.f;
        }
        if (++s3 == 3) { s3 = 0; sp ^= 1; }
    }
    __syncthreads();

    // ---- softmax over top-32 + fp16 value gather + fp32 residual ----
    const __half* vbase = valh + (size_t)slot * NKEYS * VDIM;
#pragma unroll
    for (int t = 0; t < 8; t++) {
        const int q = wid * 8 + t;
        const int qg_ = q0 + q;
        unsigned p = hp[q * 33 + lane];
        float s = unpackscore(p);
        int  ki = (int)(p & 0x1FFFu);
        float m = s;
#pragma unroll
        for (int o = 16; o; o >>= 1)
            m = fmaxf(m, __shfl_xor_sync(0xffffffffu, m, o));
        float e = __expf(s - m);
        float sum = e;
#pragma unroll
        for (int o = 16; o; o >>= 1) sum += __shfl_xor_sync(0xffffffffu, sum, o);
        float w = e / sum;

        float2 acc[2][4];
#pragma unroll
        for (int j = 0; j < 2; j++)
#pragma unroll
            for (int u = 0; u < 4; u++) acc[j][u] = make_float2(0.f, 0.f);

#pragma unroll 4
        for (int k = 0; k < TOPK; k++) {
            float wk = __shfl_sync(0xffffffffu, w, k);
            int   ik = __shfl_sync(0xffffffffu, ki, k);
            const uint4* vr = (const uint4*)(vbase + (size_t)ik * VDIM);
#pragma unroll
            for (int j = 0; j < 2; j++) {
                uint4 u4 = vr[lane + j * 32];
                unsigned uu[4] = {u4.x, u4.y, u4.z, u4.w};
#pragma unroll
                for (int u = 0; u < 4; u++) {
                    float2 f = __half22float2(*(__half2*)&uu[u]);
                    acc[j][u].x += wk * f.x;
                    acc[j][u].y += wk * f.y;
                }
            }
        }
        const float2* rr = (const float2*)(g_resid + (size_t)qg_ * VDIM);
        float2* op = (float2*)(out + ((size_t)qg_ * NSLOTS + slot) * VDIM);
#pragma unroll
        for (int j = 0; j < 2; j++)
#pragma unroll
            for (int u = 0; u < 4; u++) {
                int idx = (lane + j * 32) * 4 + u;
                float2 r = rr[idx];
                op[idx] = make_float2(acc[j][u].x + r.x, acc[j][u].y + r.y);
            }
    }
}

// ---------------------------------------------------------------------------
extern "C" void kernel_launch(void* const* d_in, const int* in_sizes, int n_in,
                              void* d_out, int out_size)
{
    const float* x      = (const float*)d_in[0];
    const float* keys   = (const float*)d_in[1];
    const float* values = (const float*)d_in[2];
    const float* wq     = (const float*)d_in[3];
    const float* bq     = (const float*)d_in[4];
    const float* wr     = (const float*)d_in[5];
    const float* br     = (const float*)d_in[6];
    float* out = (float*)d_out;

    float *qp, *rp;
    __half *kh, *vh;
    cudaGetSymbolAddress((void**)&qp, g_q);
    cudaGetSymbolAddress((void**)&rp, g_resid);
    cudaGetSymbolAddress((void**)&kh, g_keysh);
    cudaGetSymbolAddress((void**)&vh, g_valh);

    normalize_keys_h<<<NSLOTS * NKEYS / 8, 256>>>(keys, kh);
    values_to_half<<<NSLOTS * NKEYS * VDIM / (256 * 8), 256>>>(values, vh);
    gemm_nt_bias<<<dim3(KDIM / 64, NQ / 64), 128>>>(x, wq, bq, qp, NQ, KDIM, IN_DIM);
    gemm_nt_bias<<<dim3(VDIM / 64, NQ / 64), 128>>>(qp, wr, br, rp, NQ, VDIM, KDIM);

    cudaFuncSetAttribute(fused_slot,
                         cudaFuncAttributeMaxDynamicSharedMemorySize,
                         FUSED_SMEM_BYTES);
    fused_slot<<<dim3(NQ / 128, NSLOTS), 512, FUSED_SMEM_BYTES>>>(kh, vh, out);
}